// round 7
// baseline (speedup 1.0000x reference)
#include <cuda_runtime.h>

// CausalConv1d (depthwise, K=4) + SiLU
// x: (B=4, S=8192, D=2048) fp32, w: (D, 1, 4) fp32, out: (B, S, D) fp32
// y[b,s,d] = silu( sum_{k=0..3} x[b, s-3+k, d] * w[d,0,k] )   (causal left zero-pad)
//
// R4 shape (best, 81.3us): T=8 outputs/thread, 11 front-batched evict-first
// LDG.128, tanh-SiLU, 7 CTAs/SM.
// R6 delta: stores use write-through (__stwt) instead of evict-first (__stcs):
// output is never re-read, so don't hold dirty lines in L2 — free capacity and
// eviction bandwidth for the x read stream.

constexpr int B_ = 4;
constexpr int S_ = 8192;
constexpr int D_ = 2048;
constexpr int D4 = D_ / 4;      // 512 float4 lanes along channel dim
constexpr int T_ = 8;           // s-positions per thread
constexpr int THREADS = 128;

// silu(v) = h + h*tanh(h), h = v/2.  One MUFU op.
__device__ __forceinline__ float silu_f(float v) {
    float h = 0.5f * v;
    float t;
    asm("tanh.approx.f32 %0, %1;" : "=f"(t) : "f"(h));
    return fmaf(h, t, h);
}

__global__ __launch_bounds__(THREADS, 7)
void causal_conv1d_silu_kernel(const float4* __restrict__ x,
                               const float4* __restrict__ w4,   // [D] float4: 4 taps / channel
                               float4* __restrict__ y)
{
    const int d4 = blockIdx.x * THREADS + threadIdx.x;   // float4 channel group
    const int s0 = blockIdx.y * T_;
    const int b  = blockIdx.z;

    const float4* xb = x + ((b * S_ + s0) * D4 + d4);
    float4*       yb = y + ((b * S_ + s0) * D4 + d4);

    // ---- Front-batched loads: 11 independent LDG.128, evict-first ----
    float4 r[T_ + 3];
    if (blockIdx.y != 0) {
        r[0] = __ldcs(xb - 3 * D4);
        r[1] = __ldcs(xb - 2 * D4);
        r[2] = __ldcs(xb - 1 * D4);
    } else {
        const float4 z = make_float4(0.f, 0.f, 0.f, 0.f);
        r[0] = z; r[1] = z; r[2] = z;
    }
#pragma unroll
    for (int t = 0; t < T_; ++t)
        r[t + 3] = __ldcs(xb + t * D4);

    // Taps: w4[c] = (k0,k1,k2,k3) of channel c.
    const float4* wb = w4 + d4 * 4;
    const float4 wA = __ldg(wb + 0);
    const float4 wB = __ldg(wb + 1);
    const float4 wC = __ldg(wb + 2);
    const float4 wD = __ldg(wb + 3);

#pragma unroll
    for (int t = 0; t < T_; ++t) {
        float ox = fmaf(r[t].x, wA.x, fmaf(r[t+1].x, wA.y, fmaf(r[t+2].x, wA.z, r[t+3].x * wA.w)));
        float oy = fmaf(r[t].y, wB.x, fmaf(r[t+1].y, wB.y, fmaf(r[t+2].y, wB.z, r[t+3].y * wB.w)));
        float oz = fmaf(r[t].z, wC.x, fmaf(r[t+1].z, wC.y, fmaf(r[t+2].z, wC.z, r[t+3].z * wC.w)));
        float ow = fmaf(r[t].w, wD.x, fmaf(r[t+1].w, wD.y, fmaf(r[t+2].w, wD.z, r[t+3].w * wD.w)));

        float4 o;
        o.x = silu_f(ox);
        o.y = silu_f(oy);
        o.z = silu_f(oz);
        o.w = silu_f(ow);

        // Write-through streaming store: never re-read, don't pollute L2.
        __stwt(yb + t * D4, o);
    }
}

extern "C" void kernel_launch(void* const* d_in, const int* in_sizes, int n_in,
                              void* d_out, int out_size)
{
    const float4* x  = (const float4*)d_in[0];
    const float4* w4 = (const float4*)d_in[1];
    float4* y = (float4*)d_out;

    dim3 block(THREADS, 1, 1);
    dim3 grid(D4 / THREADS, S_ / T_, B_);   // (4, 1024, 4) = 16384 CTAs
    causal_conv1d_silu_kernel<<<grid, block>>>(x, w4, y);
}

// round 8
// speedup vs baseline: 1.0727x; 1.0727x over previous
#include <cuda_runtime.h>

// CausalConv1d (depthwise, K=4) + SiLU — FINAL (R4 configuration, best of record).
// x: (B=4, S=8192, D=2048) fp32, w: (D, 1, 4) fp32, out: (B, S, D) fp32
// y[b,s,d] = silu( sum_{k=0..3} x[b, s-3+k, d] * w[d,0,k] )   (causal left zero-pad)
//
// Design (validated over R1–R6):
//  - T=8 outputs/thread, one float4 channel-group/thread: 11 front-batched
//    independent LDG.128 (high MLP) -> fully unrolled FMA + SiLU epilogue.
//  - x reads evict-first (__ldcs): dead after <=2 touches; keeps L2 for dirty
//    output lines + halo rows. Stores evict-first (__stcs): L2 write-coalescing
//    retained (write-through regressed 8%).
//  - SiLU via tanh.approx: silu(v) = h + h*tanh(h), h=v/2 — one MUFU op.
//  - 7 CTAs/SM (72 regs): more warps proved neutral (not warp-limited).
// Measured: 81.3us, DRAM 81%, app rate 7.2 TB/s ~= 90% of spec HBM (roofline).

constexpr int B_ = 4;
constexpr int S_ = 8192;
constexpr int D_ = 2048;
constexpr int D4 = D_ / 4;      // 512 float4 lanes along channel dim
constexpr int T_ = 8;           // s-positions per thread
constexpr int THREADS = 128;

__device__ __forceinline__ float silu_f(float v) {
    float h = 0.5f * v;
    float t;
    asm("tanh.approx.f32 %0, %1;" : "=f"(t) : "f"(h));
    return fmaf(h, t, h);
}

__global__ __launch_bounds__(THREADS, 7)
void causal_conv1d_silu_kernel(const float4* __restrict__ x,
                               const float4* __restrict__ w4,   // [D] float4: 4 taps / channel
                               float4* __restrict__ y)
{
    const int d4 = blockIdx.x * THREADS + threadIdx.x;   // float4 channel group
    const int s0 = blockIdx.y * T_;
    const int b  = blockIdx.z;

    const float4* xb = x + ((b * S_ + s0) * D4 + d4);
    float4*       yb = y + ((b * S_ + s0) * D4 + d4);

    // ---- Front-batched loads: 11 independent LDG.128, evict-first ----
    float4 r[T_ + 3];
    if (blockIdx.y != 0) {
        r[0] = __ldcs(xb - 3 * D4);
        r[1] = __ldcs(xb - 2 * D4);
        r[2] = __ldcs(xb - 1 * D4);
    } else {
        const float4 z = make_float4(0.f, 0.f, 0.f, 0.f);
        r[0] = z; r[1] = z; r[2] = z;
    }
#pragma unroll
    for (int t = 0; t < T_; ++t)
        r[t + 3] = __ldcs(xb + t * D4);

    // Taps: w4[c] = (k0,k1,k2,k3) of channel c (L2-resident).
    const float4* wb = w4 + d4 * 4;
    const float4 wA = __ldg(wb + 0);
    const float4 wB = __ldg(wb + 1);
    const float4 wC = __ldg(wb + 2);
    const float4 wD = __ldg(wb + 3);

#pragma unroll
    for (int t = 0; t < T_; ++t) {
        float ox = fmaf(r[t].x, wA.x, fmaf(r[t+1].x, wA.y, fmaf(r[t+2].x, wA.z, r[t+3].x * wA.w)));
        float oy = fmaf(r[t].y, wB.x, fmaf(r[t+1].y, wB.y, fmaf(r[t+2].y, wB.z, r[t+3].y * wB.w)));
        float oz = fmaf(r[t].z, wC.x, fmaf(r[t+1].z, wC.y, fmaf(r[t+2].z, wC.z, r[t+3].z * wC.w)));
        float ow = fmaf(r[t].w, wD.x, fmaf(r[t+1].w, wD.y, fmaf(r[t+2].w, wD.z, r[t+3].w * wD.w)));

        float4 o;
        o.x = silu_f(ox);
        o.y = silu_f(oy);
        o.z = silu_f(oz);
        o.w = silu_f(ow);

        // Streaming store: output never re-read; L2 coalesces dirty lines.
        __stcs(yb + t * D4, o);
    }
}

extern "C" void kernel_launch(void* const* d_in, const int* in_sizes, int n_in,
                              void* d_out, int out_size)
{
    const float4* x  = (const float4*)d_in[0];
    const float4* w4 = (const float4*)d_in[1];
    float4* y = (float4*)d_out;

    dim3 block(THREADS, 1, 1);
    dim3 grid(D4 / THREADS, S_ / T_, B_);   // (4, 1024, 4) = 16384 CTAs
    causal_conv1d_silu_kernel<<<grid, block>>>(x, w4, y);
}